// round 1
// baseline (speedup 1.0000x reference)
#include <cuda_runtime.h>

#define NG 8
#define NT 2048
#define NH 2048
#define NE 8
#define CAP 320

#define NTOK (NG * NT)                 // 16384
#define OFF_EXPERT 0
#define OFF_PMAX   (NTOK * NE)         // 131072
#define OFF_LOGITS (OFF_PMAX + NTOK)   // 147456

// scratch: argmax expert id per token
__device__ int g_expert_id[NTOK];

__device__ __forceinline__ unsigned long long pack2(float a, float b) {
    unsigned long long r;
    asm("mov.b64 %0, {%1, %2};" : "=l"(r) : "f"(a), "f"(b));
    return r;
}
__device__ __forceinline__ void unpack2(unsigned long long v, float& a, float& b) {
    asm("mov.b64 {%0, %1}, %2;" : "=f"(a), "=f"(b) : "l"(v));
}
// packed dual-FMA: d.lo += a.lo*b.lo ; d.hi += a.hi*b.hi
__device__ __forceinline__ void fma2(unsigned long long& d,
                                     unsigned long long a,
                                     unsigned long long b) {
    asm("fma.rn.f32x2 %0, %1, %2, %0;" : "+l"(d) : "l"(a), "l"(b));
}

__device__ __forceinline__ float warp_sum(float v) {
#pragma unroll
    for (int o = 16; o > 0; o >>= 1)
        v += __shfl_xor_sync(0xffffffffu, v, o);
    return v;
}

// Kernel A: logits + softmax-max + argmax. One warp handles 2 tokens.
__global__ void __launch_bounds__(256)
router_logits_kernel(const float* __restrict__ hs,
                     const float* __restrict__ W,
                     const float* __restrict__ bias,
                     float* __restrict__ out) {
    const int lane   = threadIdx.x & 31;
    const int gwarp  = blockIdx.x * (blockDim.x >> 5) + (threadIdx.x >> 5);
    const int t0     = gwarp * 2;
    if (t0 >= NTOK) return;

    const float4* __restrict__ row0 = (const float4*)(hs + (size_t)t0 * NH);
    const float4* __restrict__ row1 = (const float4*)(hs + (size_t)(t0 + 1) * NH);
    const float4* __restrict__ Wv   = (const float4*)W;   // [NE][NH/4]

    unsigned long long acc0[NE], acc1[NE];
#pragma unroll
    for (int e = 0; e < NE; ++e) { acc0[e] = 0ull; acc1[e] = 0ull; }

#pragma unroll
    for (int it = 0; it < NH / (32 * 4); ++it) {   // 16 iterations
        const int idx = it * 32 + lane;            // float4 index, 512 per row
        float4 x0 = __ldg(row0 + idx);
        float4 x1 = __ldg(row1 + idx);
        unsigned long long x0lo = pack2(x0.x, x0.y), x0hi = pack2(x0.z, x0.w);
        unsigned long long x1lo = pack2(x1.x, x1.y), x1hi = pack2(x1.z, x1.w);
#pragma unroll
        for (int e = 0; e < NE; ++e) {
            float4 w = __ldg(Wv + e * (NH / 4) + idx);
            unsigned long long wlo = pack2(w.x, w.y), whi = pack2(w.z, w.w);
            fma2(acc0[e], x0lo, wlo);
            fma2(acc0[e], x0hi, whi);
            fma2(acc1[e], x1lo, wlo);
            fma2(acc1[e], x1hi, whi);
        }
    }

    // reduce: combine packed halves, then across lanes
    float l0[NE], l1[NE];
#pragma unroll
    for (int e = 0; e < NE; ++e) {
        float a, b;
        unpack2(acc0[e], a, b);
        l0[e] = warp_sum(a + b) + __ldg(bias + e);
        unpack2(acc1[e], a, b);
        l1[e] = warp_sum(a + b) + __ldg(bias + e);
    }

    // lane 0 finalizes token t0, lane 1 finalizes token t0+1
    if (lane < 2) {
        const float* l = (lane == 0) ? l0 : l1;
        const int t = t0 + lane;

        float mx = l[0];
        int am = 0;
#pragma unroll
        for (int e = 1; e < NE; ++e)
            if (l[e] > mx) { mx = l[e]; am = e; }   // strict > : first-max wins
        float s = 0.f;
#pragma unroll
        for (int e = 0; e < NE; ++e) s += __expf(l[e] - mx);

        out[OFF_PMAX + t] = 1.0f / s;
        g_expert_id[t] = am;

        float4* lg = (float4*)(out + OFF_LOGITS + (size_t)t * NE);
        lg[0] = make_float4(l[0], l[1], l[2], l[3]);
        lg[1] = make_float4(l[4], l[5], l[6], l[7]);
    }
}

// Kernel B: per-group cumulative capacity scan + one-hot write.
// One block per group; 256 threads x 8 tokens each.
// Per-expert counts packed as 2 x uint64 with 16-bit lanes (4 experts each).
__global__ void __launch_bounds__(256)
capacity_scan_kernel(float* __restrict__ out) {
    const int g   = blockIdx.x;
    const int tid = threadIdx.x;
    const int* __restrict__ ids = g_expert_id + g * NT;
    const int base = tid * 8;

    int eid[8], pl[8];
    unsigned long long c0 = 0ull, c1 = 0ull;
#pragma unroll
    for (int i = 0; i < 8; ++i) {
        int e = ids[base + i];
        eid[i] = e;
        if (e < 4) {
            c0 += 1ull << (e * 16);
            pl[i] = (int)((c0 >> (e * 16)) & 0xFFFF);
        } else {
            c1 += 1ull << ((e - 4) * 16);
            pl[i] = (int)((c1 >> ((e - 4) * 16)) & 0xFFFF);
        }
    }

    __shared__ unsigned long long s0[256], s1[256];
    unsigned long long i0 = c0, i1 = c1;
    s0[tid] = i0; s1[tid] = i1;
    __syncthreads();
#pragma unroll
    for (int off = 1; off < 256; off <<= 1) {
        unsigned long long a0 = 0ull, a1 = 0ull;
        if (tid >= off) { a0 = s0[tid - off]; a1 = s1[tid - off]; }
        __syncthreads();
        i0 += a0; i1 += a1;
        s0[tid] = i0; s1[tid] = i1;
        __syncthreads();
    }
    const unsigned long long ex0 = i0 - c0;  // exclusive prefix for this thread
    const unsigned long long ex1 = i1 - c1;

    float* __restrict__ dst = out + OFF_EXPERT + ((size_t)g * NT + base) * NE;
#pragma unroll
    for (int i = 0; i < 8; ++i) {
        const int e = eid[i];
        int before = (e < 4) ? (int)((ex0 >> (e * 16)) & 0xFFFF)
                             : (int)((ex1 >> ((e - 4) * 16)) & 0xFFFF);
        const int prio = before + pl[i];
        float vals[NE] = {0.f, 0.f, 0.f, 0.f, 0.f, 0.f, 0.f, 0.f};
        vals[e] = (prio <= CAP) ? 1.0f : 0.0f;
        float4* p = (float4*)(dst + (size_t)i * NE);
        p[0] = make_float4(vals[0], vals[1], vals[2], vals[3]);
        p[1] = make_float4(vals[4], vals[5], vals[6], vals[7]);
    }
}

extern "C" void kernel_launch(void* const* d_in, const int* in_sizes, int n_in,
                              void* d_out, int out_size) {
    const float* hs   = (const float*)d_in[0];
    const float* W    = (const float*)d_in[1];
    const float* bias = (const float*)d_in[2];
    float* out = (float*)d_out;

    // 16384 tokens, 2 per warp, 8 warps per block -> 1024 blocks
    router_logits_kernel<<<NTOK / 16, 256>>>(hs, W, bias, out);
    capacity_scan_kernel<<<NG, 256>>>(out);
}

// round 2
// speedup vs baseline: 1.2755x; 1.2755x over previous
#include <cuda_runtime.h>

#define NG 8
#define NT 2048
#define NH 2048
#define NE 8
#define CAP 320

#define NTOK (NG * NT)                 // 16384
#define OFF_PMAX   (NTOK * NE)         // 131072
#define OFF_LOGITS (OFF_PMAX + NTOK)   // 147456

#define TPW 8                          // tokens per warp (kernel A)
#define CHUNK 128                      // tokens per block (kernel B)

__device__ int g_expert_id[NTOK];

__device__ __forceinline__ unsigned long long pack2(float a, float b) {
    unsigned long long r;
    asm("mov.b64 %0, {%1, %2};" : "=l"(r) : "f"(a), "f"(b));
    return r;
}
__device__ __forceinline__ void unpack2(unsigned long long v, float& a, float& b) {
    asm("mov.b64 {%0, %1}, %2;" : "=f"(a), "=f"(b) : "l"(v));
}
// packed dual-FMA: d.lo += a.lo*b.lo ; d.hi += a.hi*b.hi
__device__ __forceinline__ void fma2(unsigned long long& d,
                                     unsigned long long a,
                                     unsigned long long b) {
    asm("fma.rn.f32x2 %0, %1, %2, %0;" : "+l"(d) : "l"(a), "l"(b));
}

// ---------------------------------------------------------------------------
// Kernel A: router logits GEMV. 8 tokens per warp => W loads amortized 8x.
// ---------------------------------------------------------------------------
__global__ void __launch_bounds__(128)
router_logits_kernel(const float* __restrict__ hs,
                     const float* __restrict__ W,
                     const float* __restrict__ bias,
                     float* __restrict__ out) {
    const int lane  = threadIdx.x & 31;
    const int gwarp = (blockIdx.x * blockDim.x + threadIdx.x) >> 5;
    const int t0    = gwarp * TPW;

    const float4* __restrict__ Wv = (const float4*)W;      // [NE][NH/4]

    const float4* __restrict__ rows[TPW];
#pragma unroll
    for (int k = 0; k < TPW; ++k)
        rows[k] = (const float4*)(hs + (size_t)(t0 + k) * NH);

    unsigned long long acc[TPW][NE];
#pragma unroll
    for (int k = 0; k < TPW; ++k)
#pragma unroll
        for (int e = 0; e < NE; ++e) acc[k][e] = 0ull;

#pragma unroll 4
    for (int it = 0; it < NH / (32 * 4); ++it) {            // 16 iterations
        const int idx = it * 32 + lane;                     // float4 index
        unsigned long long xlo[TPW], xhi[TPW];
#pragma unroll
        for (int k = 0; k < TPW; ++k) {
            float4 x = __ldg(rows[k] + idx);
            xlo[k] = pack2(x.x, x.y);
            xhi[k] = pack2(x.z, x.w);
        }
#pragma unroll
        for (int e = 0; e < NE; ++e) {
            float4 w = __ldg(Wv + e * (NH / 4) + idx);
            unsigned long long wlo = pack2(w.x, w.y);
            unsigned long long whi = pack2(w.z, w.w);
#pragma unroll
            for (int k = 0; k < TPW; ++k) {
                fma2(acc[k][e], xlo[k], wlo);
                fma2(acc[k][e], xhi[k], whi);
            }
        }
    }

    // collapse packed halves: v[t*8+e], 64 floats per lane
    float v[64];
#pragma unroll
    for (int k = 0; k < TPW; ++k)
#pragma unroll
        for (int e = 0; e < NE; ++e) {
            float a, b;
            unpack2(acc[k][e], a, b);
            v[k * 8 + e] = a + b;
        }

    // 5-step butterfly reduction that also distributes results:
    // after step s (off=16>>s) each lane keeps (64>>s)/2 fully-combined values.
    // Final: lane holds totals for value indices {2*lane, 2*lane+1}.
#pragma unroll
    for (int s = 0; s < 5; ++s) {
        const int off  = 16 >> s;
        const int half = 32 >> s;
        const int sel  = (lane >> (4 - s)) & 1;
#pragma unroll
        for (int i = 0; i < half; ++i) {
            float a = v[i];
            float b = v[half + i];
            float mine = sel ? b : a;
            float send = sel ? a : b;
            float recv = __shfl_xor_sync(0xffffffffu, send, off);
            v[i] = mine + recv;
        }
    }

    // lane owns logits (t, e0) and (t, e0+1) with t = t0 + lane/4, e0 = (lane%4)*2
    const int t  = t0 + (lane >> 2);
    const int e0 = (lane & 3) * 2;
    const float2 bb = *(const float2*)(bias + e0);
    const float l0 = v[0] + bb.x;
    const float l1 = v[1] + bb.y;

    // coalesced logits store: global float index OFF_LOGITS + t0*8 + 2*lane
    *(float2*)(out + OFF_LOGITS + (size_t)t0 * NE + 2 * lane) = make_float2(l0, l1);

    // max / argmax with first-max tie-break
    float mx;
    int am;
    if (l1 > l0) { mx = l1; am = e0 + 1; } else { mx = l0; am = e0; }
#pragma unroll
    for (int off = 1; off <= 2; off <<= 1) {
        float omx = __shfl_xor_sync(0xffffffffu, mx, off);
        int   oam = __shfl_xor_sync(0xffffffffu, am, off);
        if (omx > mx || (omx == mx && oam < am)) { mx = omx; am = oam; }
    }
    float s = __expf(l0 - mx) + __expf(l1 - mx);
    s += __shfl_xor_sync(0xffffffffu, s, 1);
    s += __shfl_xor_sync(0xffffffffu, s, 2);

    if ((lane & 3) == 0) {
        out[OFF_PMAX + t] = 1.0f / s;
        g_expert_id[t] = am;
    }
}

// ---------------------------------------------------------------------------
// Kernel B: capacity cumsum + one-hot. 128 blocks (one per 128-token chunk).
// Prefix over earlier chunks is recomputed from the tiny L2-hot id array.
// ---------------------------------------------------------------------------
__global__ void __launch_bounds__(128)
capacity_scan_kernel(float* __restrict__ out) {
    const int g    = blockIdx.x >> 4;          // group
    const int c    = blockIdx.x & 15;          // chunk within group
    const int tid  = threadIdx.x;
    const int lane = tid & 31;
    const int w    = tid >> 5;

    const int* __restrict__ ids = g_expert_id + g * NT;

    // --- prefix counts over tokens [0, c*CHUNK), packed 16-bit lanes ---
    unsigned long long c0 = 0ull, c1 = 0ull;
    for (int i = tid; i < c * CHUNK; i += 128) {
        int e = ids[i];
        if (e < 4) c0 += 1ull << (e * 16);
        else       c1 += 1ull << ((e - 4) * 16);
    }
#pragma unroll
    for (int off = 16; off > 0; off >>= 1) {
        c0 += __shfl_xor_sync(0xffffffffu, c0, off);
        c1 += __shfl_xor_sync(0xffffffffu, c1, off);
    }

    __shared__ unsigned long long s0[4], s1[4];
    __shared__ int wcnt[4][8];
    if (lane == 0) { s0[w] = c0; s1[w] = c1; }
    if (tid < 32) ((int*)wcnt)[tid] = 0;
    __syncthreads();

    const unsigned long long p0 = s0[0] + s0[1] + s0[2] + s0[3];
    const unsigned long long p1 = s1[0] + s1[1] + s1[2] + s1[3];

    // --- in-chunk rank via match ---
    const int e = ids[c * CHUNK + tid];
    const unsigned match  = __match_any_sync(0xffffffffu, e);
    const unsigned ltmask = (1u << lane) - 1u;
    const int rank = __popc(match & ltmask);
    if ((match & ltmask) == 0)           // lowest lane with this expert
        wcnt[w][e] = __popc(match);
    __syncthreads();

    int before_w = 0;
#pragma unroll
    for (int ww = 0; ww < 4; ++ww)
        if (ww < w) before_w += wcnt[ww][e];

    const int pre = (e < 4) ? (int)((p0 >> (e * 16)) & 0xFFFF)
                            : (int)((p1 >> ((e - 4) * 16)) & 0xFFFF);
    const int prio = pre + before_w + rank + 1;   // inclusive cumsum value
    const float keep = (prio <= CAP) ? 1.0f : 0.0f;

    float4 o0 = make_float4(e == 0 ? keep : 0.f, e == 1 ? keep : 0.f,
                            e == 2 ? keep : 0.f, e == 3 ? keep : 0.f);
    float4 o1 = make_float4(e == 4 ? keep : 0.f, e == 5 ? keep : 0.f,
                            e == 6 ? keep : 0.f, e == 7 ? keep : 0.f);
    float4* dst = (float4*)(out + ((size_t)(g * NT + c * CHUNK + tid)) * NE);
    dst[0] = o0;
    dst[1] = o1;
}

extern "C" void kernel_launch(void* const* d_in, const int* in_sizes, int n_in,
                              void* d_out, int out_size) {
    const float* hs   = (const float*)d_in[0];
    const float* W    = (const float*)d_in[1];
    const float* bias = (const float*)d_in[2];
    float* out = (float*)d_out;

    // 16384 tokens, 8 per warp, 4 warps per block -> 512 blocks
    router_logits_kernel<<<NTOK / (TPW * 4), 128>>>(hs, W, bias, out);
    // 16384 tokens / 128 per chunk -> 128 blocks
    capacity_scan_kernel<<<NTOK / CHUNK, 128>>>(out);
}